// round 2
// baseline (speedup 1.0000x reference)
#include <cuda_runtime.h>
#include <cuda_bf16.h>
#include <math.h>

#define MAX_STEPS 16
#define BATCH     256
#define VOCAB     32000
#define NROWS     (MAX_STEPS * BATCH)   // 4096
#define VOCAB4    (VOCAB / 4)           // 8000

// Per-row weighted CE partials (deterministic two-kernel reduce, no atomics).
__device__ float g_row_partial[NROWS];

// Detect whether y_true buffer is int64 or int32 and load target for row b.
// int64 little-endian with values < 2^31 => odd 32-bit words are 0.
__device__ __forceinline__ int load_target(const int* __restrict__ yt, int b) {
    bool is64 = true;
#pragma unroll
    for (int i = 0; i < 8; i++) is64 &= (yt[2 * i + 1] == 0);
    return is64 ? yt[2 * b] : yt[b];
}

__global__ void __launch_bounds__(256, 8)
row_lse_kernel(const float* __restrict__ p,
               const float* __restrict__ y_pred,
               const int*   __restrict__ y_true)
{
    const int row = blockIdx.x;           // row = n * BATCH + b
    const int b   = row & (BATCH - 1);
    const int tid = threadIdx.x;

    const float4* __restrict__ rp =
        reinterpret_cast<const float4*>(y_pred + (long long)row * VOCAB);

    // Per-thread online (max, sum exp) over this thread's strided float4 chunks.
    float m = -INFINITY;
    float s = 0.0f;

#pragma unroll 4
    for (int i = tid; i < VOCAB4; i += 256) {
        float4 v = __ldg(&rp[i]);
        float m4 = fmaxf(fmaxf(v.x, v.y), fmaxf(v.z, v.w));
        if (m4 > m) {
            s *= __expf(m - m4);   // first iter: 0 * exp(-inf) handled below
            m = m4;
        }
        s += __expf(v.x - m);
        s += __expf(v.y - m);
        s += __expf(v.z - m);
        s += __expf(v.w - m);
    }
    // Guard: if this thread saw no elements (can't happen here, but cheap)
    // s stays 0, m stays -inf; combine handles it via exp(-inf)=0.

    // Warp-level combine of (m, s)
    const unsigned FULL = 0xFFFFFFFFu;
#pragma unroll
    for (int off = 16; off > 0; off >>= 1) {
        float mo = __shfl_xor_sync(FULL, m, off);
        float so = __shfl_xor_sync(FULL, s, off);
        float M  = fmaxf(m, mo);
        // exp(-inf - M) = 0 so -inf lanes contribute nothing
        s = s * __expf(m - M) + so * __expf(mo - M);
        m = M;
    }

    // Cross-warp combine via shared memory (8 warps)
    __shared__ float sm_m[8];
    __shared__ float sm_s[8];
    const int warp = tid >> 5;
    const int lane = tid & 31;
    if (lane == 0) { sm_m[warp] = m; sm_s[warp] = s; }
    __syncthreads();

    if (tid == 0) {
        float M = sm_m[0];
#pragma unroll
        for (int w = 1; w < 8; w++) M = fmaxf(M, sm_m[w]);
        float S = 0.0f;
#pragma unroll
        for (int w = 0; w < 8; w++) S += sm_s[w] * __expf(sm_m[w] - M);

        float lse = M + __logf(S);
        int   tgt = load_target(y_true, b);
        float xt  = __ldg(y_pred + (long long)row * VOCAB + tgt);
        float ce  = lse - xt;
        g_row_partial[row] = p[row] * ce;
    }
}

__global__ void __launch_bounds__(256, 1)
final_reduce_kernel(float* __restrict__ out)
{
    const int tid = threadIdx.x;
    float acc = 0.0f;
#pragma unroll
    for (int i = tid; i < NROWS; i += 256) acc += g_row_partial[i];

    const unsigned FULL = 0xFFFFFFFFu;
#pragma unroll
    for (int off = 16; off > 0; off >>= 1)
        acc += __shfl_xor_sync(FULL, acc, off);

    __shared__ float sm[8];
    const int warp = tid >> 5;
    const int lane = tid & 31;
    if (lane == 0) sm[warp] = acc;
    __syncthreads();
    if (tid == 0) {
        float total = 0.0f;
#pragma unroll
        for (int w = 0; w < 8; w++) total += sm[w];
        out[0] = total / (float)BATCH;
    }
}

extern "C" void kernel_launch(void* const* d_in, const int* in_sizes, int n_in,
                              void* d_out, int out_size)
{
    // Route inputs by element count (robust to metadata ordering):
    //   p: 4096, y_pred: 131072000, y_true: 256 (int32 or int64)
    const float* p      = nullptr;
    const float* y_pred = nullptr;
    const int*   y_true = nullptr;
    for (int i = 0; i < n_in; i++) {
        if (in_sizes[i] == NROWS)            p      = (const float*)d_in[i];
        else if (in_sizes[i] > 1000000)      y_pred = (const float*)d_in[i];
        else                                 y_true = (const int*)d_in[i];
    }

    row_lse_kernel<<<NROWS, 256>>>(p, y_pred, y_true);
    final_reduce_kernel<<<1, 256>>>((float*)d_out);
}